// round 1
// baseline (speedup 1.0000x reference)
#include <cuda_runtime.h>
#include <math_constants.h>
#include <cstdint>

// ---------------------------------------------------------------------------
// VectorQuantizer: B=4,H=8,R=8,C=512,K=128,S=1024
// Forward values: quantized = c[h, argmin_s ||v-c_s||^2, :]
//                 z, errs2 = relu(min dist), l_commit = sum(errs2)/(B*R*C),
//                 l_codebook = 0 (stop-gradient identity kills it numerically)
// ---------------------------------------------------------------------------

namespace {
constexpr int Bn = 4, Hn = 8, Rn = 8, Cn = 512, Kn = 128, Sn = 1024;
constexpr int RC = Rn * Cn;                 // 4096
constexpr int NV = Bn * Hn * Rn * Cn;       // 131072 vectors
constexpr int VT = 128;                     // vectors per block
constexpr int CT = 128;                     // codewords per tile
constexpr int NBLK = NV / VT;               // 1024
constexpr int PAD = 132;                    // floats per padded row (528B)
constexpr int K4 = Kn / 4;                  // 32 float4 per row
constexpr size_t SMEMB = (size_t)2 * VT * PAD * sizeof(float); // 135168 B

constexpr long long OFF_Q  = 0;
constexpr long long OFF_Z  = (long long)NV * Kn;   // 16777216
constexpr long long OFF_LC = OFF_Z + NV;           // 16908288
constexpr long long OFF_LB = OFF_LC + 1;           // 16908289
constexpr long long OFF_E  = OFF_LB + 1;           // 16908290
}

__device__ float g_cb[Hn * Sn * Kn];   // codebook (4 MB)
__device__ float g_cn2[Hn * Sn];       // ||c||^2
__device__ float g_bsum[NBLK];         // per-block errs2 sums
__device__ int   g_z[NV];              // argmin indices (int form for gather)

// ---------------------------------------------------------------------------
// Kernel 1: codebook = c_sum / max(c_count, 0.01); also ||c||^2
// ---------------------------------------------------------------------------
__global__ void k_codebook(const float* __restrict__ c_sum,
                           const float* __restrict__ c_count) {
    int hs = blockIdx.x;           // 0..H*S-1
    int t  = threadIdx.x;          // 0..127 (= K)
    float inv = 1.0f / fmaxf(c_count[hs], 0.01f);
    float v = c_sum[(size_t)hs * Kn + t] * inv;
    g_cb[(size_t)hs * Kn + t] = v;

    __shared__ float red[128];
    red[t] = v * v;
    __syncthreads();
    #pragma unroll
    for (int s = 64; s > 0; s >>= 1) {
        if (t < s) red[t] += red[t + s];
        __syncthreads();
    }
    if (t == 0) g_cn2[hs] = red[0];
}

// ---------------------------------------------------------------------------
// Kernel 2: distances + argmin. 256 threads = 16x16; 8x8 register tile.
// Thread (ty,tx): vectors {ty+16i}, codewords {tx+16j} (interleaved rows so
// adjacent lanes hit adjacent padded rows -> conflict-free LDS.128).
// ---------------------------------------------------------------------------
__global__ void __launch_bounds__(256, 1)
k_dist(const float* __restrict__ vecs, float* __restrict__ out) {
    extern __shared__ float smem[];
    float* sv = smem;                 // VT * PAD
    float* sc = smem + VT * PAD;      // CT * PAD
    __shared__ float snp[256];
    __shared__ float ered[256];

    const int tid = threadIdx.x;
    const int tx = tid & 15;
    const int ty = tid >> 4;
    const int blk = blockIdx.x;
    const int h = (blk / (RC / VT)) % Hn;   // RC/VT = 32 blocks per (b,h,r)... (n/RC)%H

    // ---- load vector tile (coalesced float4, padded rows) ----
    const float4* gv = (const float4*)(vecs + (size_t)blk * VT * Kn);
    for (int idx = tid; idx < VT * K4; idx += 256) {
        int v = idx >> 5, k4 = idx & 31;
        *(float4*)&sv[v * PAD + k4 * 4] = gv[idx];
    }

    float minv[8];
    int   mini[8];
    #pragma unroll
    for (int i = 0; i < 8; i++) { minv[i] = CUDART_INF_F; mini[i] = 0; }

    for (int ct = 0; ct < Sn / CT; ct++) {
        const int cwbase = ct * CT;
        __syncthreads();  // prior tile fully consumed (also covers sv load on ct=0... need sv visible too)
        const float4* gc = (const float4*)(g_cb + ((size_t)h * Sn + cwbase) * Kn);
        for (int idx = tid; idx < CT * K4; idx += 256) {
            int v = idx >> 5, k4 = idx & 31;
            *(float4*)&sc[v * PAD + k4 * 4] = gc[idx];
        }
        __syncthreads();

        float acc[8][8];
        #pragma unroll
        for (int i = 0; i < 8; i++)
            #pragma unroll
            for (int j = 0; j < 8; j++) acc[i][j] = 0.0f;

        for (int k4 = 0; k4 < K4; k4++) {
            float4 va[8];
            #pragma unroll
            for (int i = 0; i < 8; i++)
                va[i] = *(const float4*)&sv[(ty + 16 * i) * PAD + k4 * 4];
            #pragma unroll
            for (int j = 0; j < 8; j++) {
                float4 vb = *(const float4*)&sc[(tx + 16 * j) * PAD + k4 * 4];
                #pragma unroll
                for (int i = 0; i < 8; i++) {
                    acc[i][j] = fmaf(va[i].x, vb.x, acc[i][j]);
                    acc[i][j] = fmaf(va[i].y, vb.y, acc[i][j]);
                    acc[i][j] = fmaf(va[i].z, vb.z, acc[i][j]);
                    acc[i][j] = fmaf(va[i].w, vb.w, acc[i][j]);
                }
            }
        }

        // dist(without vn2) = cn2 - 2*dot ; ascending cw order -> first-min ties
        #pragma unroll
        for (int j = 0; j < 8; j++) {
            int cw = cwbase + tx + 16 * j;
            float cn2 = g_cn2[h * Sn + cw];
            #pragma unroll
            for (int i = 0; i < 8; i++) {
                float d = fmaf(-2.0f, acc[i][j], cn2);
                if (d < minv[i]) { minv[i] = d; mini[i] = cw; }
            }
        }
    }

    // ---- epilogue: cross-thread argmin reduce, norms, errs2 ----
    __syncthreads();   // done reading sc; reuse as scratch
    float* rv = sc;                         // [VT][16]
    int*   ri = (int*)(sc + VT * 16);       // [VT][16]
    #pragma unroll
    for (int i = 0; i < 8; i++) {
        int row = ty + 16 * i;
        rv[row * 16 + tx] = minv[i];
        ri[row * 16 + tx] = mini[i];
    }
    // vector norms: 2 threads per vector (reads sv, disjoint from scratch)
    {
        int v = tid >> 1, half = tid & 1;
        const float* p = &sv[v * PAD + half * 64];
        float s = 0.0f;
        #pragma unroll
        for (int kk = 0; kk < 64; kk += 4) {
            float4 x = *(const float4*)&p[kk];
            s += x.x * x.x + x.y * x.y + x.z * x.z + x.w * x.w;
        }
        snp[tid] = s;
    }
    __syncthreads();

    float err = 0.0f;
    if (tid < VT) {
        float nrm = snp[2 * tid] + snp[2 * tid + 1];
        float best = CUDART_INF_F; int bidx = 0x7fffffff;
        #pragma unroll
        for (int t = 0; t < 16; t++) {
            float v = rv[tid * 16 + t];
            int   ix = ri[tid * 16 + t];
            if (v < best || (v == best && ix < bidx)) { best = v; bidx = ix; }
        }
        err = fmaxf(nrm + best, 0.0f);
        int n = blk * VT + tid;
        g_z[n] = bidx;
        out[OFF_Z + n] = (float)bidx;
        out[OFF_E + n] = err;
    }
    ered[tid] = (tid < VT) ? err : 0.0f;
    __syncthreads();
    #pragma unroll
    for (int s = 128; s > 0; s >>= 1) {
        if (tid < s) ered[tid] += ered[tid + s];
        __syncthreads();
    }
    if (tid == 0) g_bsum[blk] = ered[0];
}

// ---------------------------------------------------------------------------
// Kernel 3: gather quantized = c[h, z[n], :]  (8 vectors / block, float4)
// ---------------------------------------------------------------------------
__global__ void k_gather(float* __restrict__ out) {
    int n = blockIdx.x * 8 + (threadIdx.x >> 5);
    int lane = threadIdx.x & 31;
    int z = g_z[n];
    int h = (n / RC) % Hn;
    float4 v = ((const float4*)g_cb)[(size_t)(h * Sn + z) * 32 + lane];
    ((float4*)out)[(size_t)n * 32 + lane] = v;   // OFF_Q = 0
}

// ---------------------------------------------------------------------------
// Kernel 4: deterministic final reduce -> l_commit, l_codebook
// ---------------------------------------------------------------------------
__global__ void k_final(float* __restrict__ out) {
    __shared__ float red[256];
    int t = threadIdx.x;
    float s = 0.0f;
    for (int i = t; i < NBLK; i += 256) s += g_bsum[i];
    red[t] = s;
    __syncthreads();
    #pragma unroll
    for (int k = 128; k > 0; k >>= 1) {
        if (t < k) red[t] += red[t + k];
        __syncthreads();
    }
    if (t == 0) {
        out[OFF_LC] = red[0] / (float)(Bn * Rn * Cn);
        out[OFF_LB] = 0.0f;
    }
}

// ---------------------------------------------------------------------------
extern "C" void kernel_launch(void* const* d_in, const int* in_sizes, int n_in,
                              void* d_out, int out_size) {
    const float* vecs    = (const float*)d_in[0];
    const float* c_sum   = (const float*)d_in[1];
    const float* c_count = (const float*)d_in[2];
    float* out = (float*)d_out;

    cudaFuncSetAttribute(k_dist, cudaFuncAttributeMaxDynamicSharedMemorySize,
                         (int)SMEMB);

    k_codebook<<<Hn * Sn, 128>>>(c_sum, c_count);
    k_dist<<<NBLK, 256, SMEMB>>>(vecs, out);
    k_gather<<<NV / 8, 256>>>(out);
    k_final<<<1, 256>>>(out);
}

// round 6
// speedup vs baseline: 2.2608x; 2.2608x over previous
#include <cuda_runtime.h>
#include <cuda_fp16.h>
#include <math_constants.h>
#include <cstdint>

// ---------------------------------------------------------------------------
// VectorQuantizer B=4,H=8,R=8,C=512,K=128,S=1024 — HMMA (mma.sync) split-fp16
// Single K=384 GEMM: A=[vh | vh*2^-6 | vl'*2^-6], B=[ch | cl'*2^-5 | ch*2^-5]
// -> dot = v.c - vl.cl (fp32-equivalent). d = ||c||^2 - 2 dot ; argmin.
// B stored row-major [N][K] -> ldmatrix WITHOUT .trans gives the col-fragment.
// ---------------------------------------------------------------------------

namespace {
constexpr int Hn = 8, Sn = 1024, Kn = 128;
constexpr int RC = 4096, NV = 131072, NBLK = 1024;
constexpr long long OFF_Z  = (long long)NV * Kn;   // 16777216
constexpr long long OFF_LC = OFF_Z + NV;
constexpr long long OFF_LB = OFF_LC + 1;
constexpr long long OFF_E  = OFF_LB + 1;

constexpr int LDA  = 392;        // halves per row (784 B, rows hit distinct 16B banks)
constexpr int ROWB = 784;
constexpr int CH_ROWS = 64;      // codewords per chunk
constexpr int NCHUNK  = 16;
constexpr int CH_BYTES = CH_ROWS * ROWB;   // 50176

constexpr int SM_A   = 0;                     // 128*784 = 100352
constexpr int SM_B   = 100352;                // 2 * 50176
constexpr int SM_CN2 = 200704;                // 4096
constexpr int SM_VN2 = 204800;                // 512
constexpr int SM_BV  = 205312;                // 128*2*4
constexpr int SM_BI  = 206336;                // 128*2*4
constexpr int SM_RED = 207360;                // 512
constexpr int DYN    = 207872;
}

__device__ float g_cb[Hn * Sn * Kn];                       // fp32 codebook (gather)
__device__ float g_cn2[Hn * Sn];
__device__ float g_bsum[NBLK];
__device__ int   g_z[NV];
__device__ __align__(16) unsigned char g_bblob[(size_t)Hn * Sn * ROWB]; // 6.4MB

// ---------------- PTX helpers ----------------
__device__ __forceinline__ uint32_t s2u(const void* p) {
    uint32_t a;
    asm("{ .reg .u64 t; cvta.to.shared.u64 t, %1; cvt.u32.u64 %0, t; }" : "=r"(a) : "l"(p));
    return a;
}
__device__ __forceinline__ void cpa16(uint32_t dst, const void* src) {
    asm volatile("cp.async.cg.shared.global [%0], [%1], 16;" :: "r"(dst), "l"(src) : "memory");
}
__device__ __forceinline__ void cpa_commit() {
    asm volatile("cp.async.commit_group;" ::: "memory");
}
template <int N>
__device__ __forceinline__ void cpa_wait() {
    asm volatile("cp.async.wait_group %0;" :: "n"(N) : "memory");
}
__device__ __forceinline__ void ldsm4(uint32_t* r, uint32_t a) {
    asm volatile("ldmatrix.sync.aligned.m8n8.x4.shared.b16 {%0,%1,%2,%3}, [%4];"
                 : "=r"(r[0]), "=r"(r[1]), "=r"(r[2]), "=r"(r[3]) : "r"(a));
}
__device__ __forceinline__ void mma16816(float* d, const uint32_t* a, uint32_t b0, uint32_t b1) {
    asm volatile(
        "mma.sync.aligned.m16n8k16.row.col.f32.f16.f16.f32 "
        "{%0,%1,%2,%3}, {%4,%5,%6,%7}, {%8,%9}, {%0,%1,%2,%3};"
        : "+f"(d[0]), "+f"(d[1]), "+f"(d[2]), "+f"(d[3])
        : "r"(a[0]), "r"(a[1]), "r"(a[2]), "r"(a[3]), "r"(b0), "r"(b1));
}

// ---------------------------------------------------------------------------
// Kernel 1: codebook = c_sum / max(c_count, 0.01) and ||c||^2
// ---------------------------------------------------------------------------
__global__ void k_codebook(const float* __restrict__ c_sum, const float* __restrict__ c_count) {
    int hs = blockIdx.x, t = threadIdx.x;
    float inv = 1.0f / fmaxf(c_count[hs], 0.01f);
    float v = c_sum[(size_t)hs * Kn + t] * inv;
    g_cb[(size_t)hs * Kn + t] = v;
    __shared__ float red[128];
    red[t] = v * v;
    __syncthreads();
    #pragma unroll
    for (int s = 64; s > 0; s >>= 1) {
        if (t < s) red[t] += red[t + s];
        __syncthreads();
    }
    if (t == 0) g_cn2[hs] = red[0];
}

// ---------------------------------------------------------------------------
// Kernel 2: padded split-fp16 codebook blob. Row (h*1024+cw): 384 halves
// [ch(128) | cl'*2^-5 (128) | ch*2^-5 (128)], stride 784B.
// ---------------------------------------------------------------------------
__global__ void k_convert() {
    int hs = blockIdx.x, k = threadIdx.x;
    float c = g_cb[(size_t)hs * Kn + k];
    __half ch = __float2half_rn(c);
    float chf = __half2float(ch);
    __half* row = (__half*)(g_bblob + (size_t)hs * ROWB);
    row[k]       = ch;
    row[128 + k] = __float2half_rn((c - chf) * 64.0f);     // cl' * 2^-5
    row[256 + k] = __float2half_rn(chf * 0.03125f);        // ch  * 2^-5
}

// ---------------------------------------------------------------------------
// Kernel 3: distances via mma.sync + argmin.
// 256 thr = 8 warps (4 M x 2 N). CTA: 128 vecs x 1024 cw (16 chunks of 64).
// ---------------------------------------------------------------------------
__global__ void __launch_bounds__(256, 1)
k_dist(const float* __restrict__ vecs, float* __restrict__ out) {
    extern __shared__ __align__(16) unsigned char sb[];
    __half* sa   = (__half*)(sb + SM_A);
    float* scn2  = (float*)(sb + SM_CN2);
    float* svn2  = (float*)(sb + SM_VN2);
    float* sbv   = (float*)(sb + SM_BV);
    int*   sbi   = (int*)(sb + SM_BI);
    float* sred  = (float*)(sb + SM_RED);

    const int tid = threadIdx.x, w = tid >> 5, ln = tid & 31;
    const int blk = blockIdx.x, h = (blk >> 5) & 7;
    const int wm = w >> 1, wn = w & 1;
    const uint32_t sbase = s2u(sb);

    // --- prefetch B chunk 0 ---
    {
        const unsigned char* src = g_bblob + (size_t)h * Sn * ROWB;
        uint32_t dst = sbase + SM_B;
        for (int idx = tid; idx < CH_BYTES / 16; idx += 256)
            cpa16(dst + idx * 16, src + idx * 16);
        cpa_commit();
    }

    // --- A tile: fp32 load, norms, split-fp16 store (stride 784B) ---
    {
        const float4* gv = (const float4*)vecs + (size_t)blk * 128 * 32;
        #pragma unroll
        for (int s = 0; s < 16; s++) {
            int row = s * 8 + w;
            float4 f = gv[(size_t)row * 32 + ln];
            float nrm = f.x * f.x + f.y * f.y + f.z * f.z + f.w * f.w;
            #pragma unroll
            for (int o = 16; o > 0; o >>= 1) nrm += __shfl_down_sync(0xffffffffu, nrm, o);
            if (ln == 0) svn2[row] = nrm;

            __half hx = __float2half_rn(f.x), hy = __float2half_rn(f.y);
            __half hz = __float2half_rn(f.z), hw = __float2half_rn(f.w);
            float fx = __half2float(hx), fy = __half2float(hy);
            float fz = __half2float(hz), fw = __half2float(hw);
            __half* r = sa + (size_t)row * LDA + 4 * ln;
            // seg0: vh
            *(__half2*)(r)     = __halves2half2(hx, hy);
            *(__half2*)(r + 2) = __halves2half2(hz, hw);
            // seg1: vh * 2^-6
            *(__half2*)(r + 128) = __halves2half2(__float2half_rn(fx * 0.015625f),
                                                  __float2half_rn(fy * 0.015625f));
            *(__half2*)(r + 130) = __halves2half2(__float2half_rn(fz * 0.015625f),
                                                  __float2half_rn(fw * 0.015625f));
            // seg2: vl' * 2^-6 = (v - vh) * 32
            *(__half2*)(r + 256) = __halves2half2(__float2half_rn((f.x - fx) * 32.0f),
                                                  __float2half_rn((f.y - fy) * 32.0f));
            *(__half2*)(r + 258) = __halves2half2(__float2half_rn((f.z - fz) * 32.0f),
                                                  __float2half_rn((f.w - fw) * 32.0f));
        }
    }
    for (int i = tid; i < 1024; i += 256) scn2[i] = g_cn2[h * 1024 + i];

    float best[4];
    int   bidx[4];
    #pragma unroll
    for (int i = 0; i < 4; i++) { best[i] = CUDART_INF_F; bidx[i] = 0; }

    const int bufoff[2] = {SM_B, SM_B + CH_BYTES};
    __syncthreads();   // A + cn2 visible to all before mainloop

    for (int ch = 0; ch < NCHUNK; ch++) {
        if (ch < NCHUNK - 1) {
            const unsigned char* src =
                g_bblob + ((size_t)h * Sn + (size_t)(ch + 1) * CH_ROWS) * ROWB;
            uint32_t dst = sbase + bufoff[(ch + 1) & 1];
            for (int idx = tid; idx < CH_BYTES / 16; idx += 256)
                cpa16(dst + idx * 16, src + idx * 16);
            cpa_commit();
            cpa_wait<1>();
        } else {
            cpa_wait<0>();
        }
        __syncthreads();

        const uint32_t bbase = sbase + bufoff[ch & 1];
        float acc[2][4][4];
        #pragma unroll
        for (int mt = 0; mt < 2; mt++)
            #pragma unroll
            for (int nt = 0; nt < 4; nt++)
                #pragma unroll
                for (int e = 0; e < 4; e++) acc[mt][nt][e] = 0.0f;

        #pragma unroll 4
        for (int ks = 0; ks < 24; ks++) {
            uint32_t af[2][4], bf[2][4];
            #pragma unroll
            for (int mt = 0; mt < 2; mt++) {
                uint32_t a = sbase + SM_A +
                    (((wm * 32 + mt * 16 + (ln & 15)) * LDA) + ks * 16 + (ln >> 4) * 8) * 2;
                ldsm4(af[mt], a);
            }
            #pragma unroll
            for (int ntl = 0; ntl < 2; ntl++) {
                uint32_t b = bbase +
                    (((wn * 32 + ntl * 16 + (ln & 15)) * LDA) + ks * 16 + (ln >> 4) * 8) * 2;
                ldsm4(bf[ntl], b);   // row-major [N][K] -> NON-trans = col fragment
            }
            #pragma unroll
            for (int mt = 0; mt < 2; mt++)
                #pragma unroll
                for (int nt = 0; nt < 4; nt++)
                    mma16816(acc[mt][nt], af[mt], bf[nt >> 1][nt & 1], bf[nt >> 1][(nt & 1) + 2]);
        }

        // epilogue: d = cn2 - 2*dot, running argmin (ascending cw order)
        #pragma unroll
        for (int nt = 0; nt < 4; nt++)
            #pragma unroll
            for (int cp = 0; cp < 2; cp++) {
                int cw = ch * 64 + wn * 32 + nt * 8 + 2 * (ln & 3) + cp;
                float cn2 = scn2[cw];
                #pragma unroll
                for (int mt = 0; mt < 2; mt++)
                    #pragma unroll
                    for (int hh = 0; hh < 2; hh++) {
                        float d = fmaf(-2.0f, acc[mt][nt][hh * 2 + cp], cn2);
                        int rid = mt * 2 + hh;
                        if (d < best[rid]) { best[rid] = d; bidx[rid] = cw; }
                    }
            }
        __syncthreads();   // all reads done before buffer overwrite next iter
    }

    // --- cross-lane argmin (4-lane col groups share rows) ---
    #pragma unroll
    for (int rid = 0; rid < 4; rid++) {
        #pragma unroll
        for (int o = 1; o < 4; o <<= 1) {
            float ov = __shfl_xor_sync(0xffffffffu, best[rid], o);
            int   oi = __shfl_xor_sync(0xffffffffu, bidx[rid], o);
            if (ov < best[rid] || (ov == best[rid] && oi < bidx[rid])) {
                best[rid] = ov; bidx[rid] = oi;
            }
        }
    }
    if ((ln & 3) == 0) {
        int q = ln >> 2;
        #pragma unroll
        for (int rid = 0; rid < 4; rid++) {
            int row = wm * 32 + (rid >> 1) * 16 + (rid & 1) * 8 + q;
            sbv[row * 2 + wn] = best[rid];
            sbi[row * 2 + wn] = bidx[rid];
        }
    }
    __syncthreads();

    float err = 0.0f;
    if (tid < 128) {
        float b0 = sbv[tid * 2], b1 = sbv[tid * 2 + 1];
        int   i0 = sbi[tid * 2], i1 = sbi[tid * 2 + 1];
        if (b1 < b0 || (b1 == b0 && i1 < i0)) { b0 = b1; i0 = i1; }
        err = fmaxf(svn2[tid] + b0, 0.0f);
        int n = blk * 128 + tid;
        g_z[n] = i0;
        out[OFF_Z + n] = (float)i0;
        out[OFF_E + n] = err;
        sred[tid] = err;
    }
    __syncthreads();
    #pragma unroll
    for (int st = 64; st > 0; st >>= 1) {
        if (tid < st) sred[tid] += sred[tid + st];
        __syncthreads();
    }
    if (tid == 0) g_bsum[blk] = sred[0];
}

// ---------------------------------------------------------------------------
// Kernel 4: gather quantized = c[h, z[n], :]
// ---------------------------------------------------------------------------
__global__ void k_gather(float* __restrict__ out) {
    int n = blockIdx.x * 8 + (threadIdx.x >> 5);
    int lane = threadIdx.x & 31;
    int z = g_z[n];
    int h = (n / RC) % Hn;
    float4 v = ((const float4*)g_cb)[(size_t)(h * Sn + z) * 32 + lane];
    ((float4*)out)[(size_t)n * 32 + lane] = v;
}

// ---------------------------------------------------------------------------
// Kernel 5: final reduce -> l_commit, l_codebook
// ---------------------------------------------------------------------------
__global__ void k_final(float* __restrict__ out) {
    __shared__ float red[256];
    int t = threadIdx.x;
    float s = 0.0f;
    for (int i = t; i < NBLK; i += 256) s += g_bsum[i];
    red[t] = s;
    __syncthreads();
    #pragma unroll
    for (int k = 128; k > 0; k >>= 1) {
        if (t < k) red[t] += red[t + k];
        __syncthreads();
    }
    if (t == 0) {
        out[OFF_LC] = red[0] / 16384.0f;
        out[OFF_LB] = 0.0f;
    }
}

// ---------------------------------------------------------------------------
extern "C" void kernel_launch(void* const* d_in, const int* in_sizes, int n_in,
                              void* d_out, int out_size) {
    const float* vecs    = (const float*)d_in[0];
    const float* c_sum   = (const float*)d_in[1];
    const float* c_count = (const float*)d_in[2];
    float* out = (float*)d_out;

    cudaFuncSetAttribute(k_dist, cudaFuncAttributeMaxDynamicSharedMemorySize, DYN);

    k_codebook<<<Hn * Sn, 128>>>(c_sum, c_count);
    k_convert<<<Hn * Sn, 128>>>();
    k_dist<<<NBLK, 256, DYN>>>(vecs, out);
    k_gather<<<NV / 8, 256>>>(out);
    k_final<<<1, 256>>>(out);
}